// round 3
// baseline (speedup 1.0000x reference)
#include <cuda_runtime.h>
#include <math.h>

#define BB   8
#define CC   512
#define CIN  256
#define HW   128
#define NN   4096
#define NHD  16
#define HD   32

// ---------------- scratch (__device__ globals: allocation-free) ----------------
__device__ float g_P1 [BB*NN*CC];   // pooled input1, (B,N,C)
__device__ float g_P2 [BB*NN*CC];   // pooled transformed input2 (= v), (B,N,C)
__device__ float g_Q  [BB*NN*CC];   // focused q, (B,N,C)
__device__ float g_K  [BB*NN*CC];   // focused k, (B,N,C)
__device__ float g_KV [BB*NHD*HD*HD];
__device__ float g_ATT[BB*CC*NN];   // attn pre-upsample, (B,C,N)
__device__ float g_isc[CC];         // 1/softplus(scale_param)

// ---------------- helpers ----------------
__device__ __forceinline__ float lrelu(float x){ return x >= 0.f ? x : 0.1f*x; }

__device__ __forceinline__ unsigned long long ffma2(unsigned long long a,
                                                    unsigned long long b,
                                                    unsigned long long c){
    unsigned long long d;
    asm("fma.rn.f32x2 %0, %1, %2, %3;" : "=l"(d) : "l"(a), "l"(b), "l"(c));
    return d;
}
__device__ __forceinline__ unsigned long long pack2(float x, float y){
    unsigned long long r; asm("mov.b64 %0, {%1,%2};" : "=l"(r) : "f"(x), "f"(y)); return r;
}
__device__ __forceinline__ void unpack2(unsigned long long v, float &x, float &y){
    asm("mov.b64 {%0,%1}, %2;" : "=f"(x), "=f"(y) : "l"(v));
}

// ---------------- K0: inverse softplus scale ----------------
__global__ void k_scale(const float* __restrict__ sp){
    int c = threadIdx.x;
    float s = sp[c];
    float v = (s > 20.f) ? s : log1pf(expf(s));
    g_isc[c] = 1.f / v;
}

// ---------------- K1: 2x2 max+mean pool of input1 -> (B,N,C) ----------------
__global__ void __launch_bounds__(256) k_pool1(const float* __restrict__ in1){
    __shared__ float tile[64][65];
    int ny = blockIdx.x, c0 = blockIdx.y * 64, b = blockIdx.z;
    int tid = threadIdx.x;
    #pragma unroll
    for (int p = 0; p < 16; p++){
        int l = p*256 + tid;
        int nx = l & 63, cc = l >> 6;
        const float* base = in1 + (((b*CC + c0+cc)*HW + 2*ny)*HW + 2*nx);
        float2 r0 = *(const float2*)base;
        float2 r1 = *(const float2*)(base + HW);
        float m = fmaxf(fmaxf(r0.x, r0.y), fmaxf(r1.x, r1.y));
        float s = (r0.x + r0.y + r1.x + r1.y) * 0.25f;
        tile[cc][nx] = m + s;
    }
    __syncthreads();
    #pragma unroll
    for (int p = 0; p < 16; p++){
        int l = p*256 + tid;
        int c = l & 63, nx = l >> 6;
        g_P1[(b*NN + ny*64 + nx)*CC + c0 + c] = tile[c][nx];
    }
}

// ---------------- K2: fused w_in GEMM + bias + 2x2 pool -> (B,N,C) ----------------
// M=128 o x 128 pixels per block, K=256, f32x2 packed FMA (FFMA2).
// B-tile columns are permuted so each pooled pixel's 4 sub-pixels are adjacent.
__global__ void __launch_bounds__(256) k_gemm_pool(const float* __restrict__ in2,
                                                  const float* __restrict__ w_in,
                                                  const float* __restrict__ b_in){
    __shared__ float As[32][132];   // As[k][o]
    __shared__ float Bs[32][128];   // Bs[k][px*4 + sy*2 + sx]
    __shared__ float bias[128];
    int pt = blockIdx.x;            // 0..127 : 32 pooled pixels each
    int o0 = blockIdx.y * 128;
    int b  = blockIdx.z;
    int n0 = pt * 32;
    int ny = n0 >> 6;
    int nx0 = n0 & 63;
    int tid = threadIdx.x;
    int tx = tid & 15, ty = tid >> 4;

    if (tid < 128) bias[tid] = b_in[o0 + tid];

    unsigned long long acc[4][8];   // [o-pair][pixel col] packed f32x2 over o
    #pragma unroll
    for (int i = 0; i < 4; i++)
        #pragma unroll
        for (int j = 0; j < 8; j++) acc[i][j] = 0ull;

    for (int kt = 0; kt < 8; kt++){
        int kbase = kt * 32;
        #pragma unroll
        for (int p = 0; p < 8; p++){            // A: 128 o x 32 k (transposed store)
            int l = p*256 + tid;
            int kk2 = l & 15, o = l >> 4;
            float2 w = *(const float2*)&w_in[(o0+o)*CIN + kbase + 2*kk2];
            As[2*kk2  ][o] = w.x;
            As[2*kk2+1][o] = w.y;
        }
        #pragma unroll
        for (int p = 0; p < 8; p++){            // B: 32 k x 128 pix (permuted)
            int l = p*256 + tid;
            int j2 = l & 31, sy = (l >> 5) & 1, k = l >> 6;
            float2 v = *(const float2*)&in2[((b*CIN + kbase + k)*HW + (2*ny + sy))*HW
                                            + 2*nx0 + 2*j2];
            Bs[k][j2*4 + sy*2    ] = v.x;
            Bs[k][j2*4 + sy*2 + 1] = v.y;
        }
        __syncthreads();
        #pragma unroll
        for (int k = 0; k < 32; k++){
            unsigned long long a2[4];
            #pragma unroll
            for (int i = 0; i < 4; i++)
                a2[i] = *(const unsigned long long*)&As[k][ty*8 + 2*i];
            float4 bl = *(const float4*)&Bs[k][tx*8];
            float4 bh = *(const float4*)&Bs[k][tx*8 + 4];
            float bv[8] = {bl.x, bl.y, bl.z, bl.w, bh.x, bh.y, bh.z, bh.w};
            #pragma unroll
            for (int j = 0; j < 8; j++){
                unsigned long long bd = pack2(bv[j], bv[j]);
                #pragma unroll
                for (int i = 0; i < 4; i++) acc[i][j] = ffma2(a2[i], bd, acc[i][j]);
            }
        }
        __syncthreads();
    }
    // epilogue: +bias, pool 4 sub-pixels (max + mean), write float4s
    float res[2][8];
    #pragma unroll
    for (int i = 0; i < 4; i++){
        float vlo[8], vhi[8];
        #pragma unroll
        for (int j = 0; j < 8; j++) unpack2(acc[i][j], vlo[j], vhi[j]);
        float blo = bias[ty*8 + 2*i], bhi = bias[ty*8 + 2*i + 1];
        #pragma unroll
        for (int g = 0; g < 2; g++){
            float m0 = -3.0e38f, s0 = 0.f, m1 = -3.0e38f, s1 = 0.f;
            #pragma unroll
            for (int s = 0; s < 4; s++){
                float t0 = vlo[g*4+s] + blo;
                float t1 = vhi[g*4+s] + bhi;
                m0 = fmaxf(m0, t0); s0 += t0;
                m1 = fmaxf(m1, t1); s1 += t1;
            }
            res[g][2*i  ] = m0 + 0.25f*s0;
            res[g][2*i+1] = m1 + 0.25f*s1;
        }
    }
    #pragma unroll
    for (int g = 0; g < 2; g++){
        float* dst = &g_P2[(b*NN + n0 + tx*2 + g)*CC + o0 + ty*8];
        *(float4*)(dst    ) = make_float4(res[g][0], res[g][1], res[g][2], res[g][3]);
        *(float4*)(dst + 4) = make_float4(res[g][4], res[g][5], res[g][6], res[g][7]);
    }
}

// ---------------- K3: q/k = focus(lrelu(p + pos) / scale), warp per row ----------------
__global__ void __launch_bounds__(256) k_focus(const float* __restrict__ pos1,
                                               const float* __restrict__ pos2){
    int warp = threadIdx.x >> 5, lane = threadIdx.x & 31;
    int r = blockIdx.x * 8 + warp;
    int b = r >> 12, n = r & (NN - 1);
    const float* p1 = &g_P1[(b*NN + n)*CC];
    const float* p2 = &g_P2[(b*NN + n)*CC];
    const float* q1 = &pos1[n*CC];
    const float* q2 = &pos2[n*CC];
    float tq3[16], tk3[16];
    float s2q = 0.f, s6q = 0.f, s2k = 0.f, s6k = 0.f;
    #pragma unroll
    for (int i = 0; i < 4; i++){
        int c = i*128 + lane*4;
        float4 a  = *(const float4*)(p1 + c);
        float4 pa = *(const float4*)(q1 + c);
        float4 kk = *(const float4*)(p2 + c);
        float4 pk = *(const float4*)(q2 + c);
        float4 is = *(const float4*)(g_isc + c);
        float ta[4] = { lrelu(a.x + pa.x)*is.x, lrelu(a.y + pa.y)*is.y,
                        lrelu(a.z + pa.z)*is.z, lrelu(a.w + pa.w)*is.w };
        float tb[4] = { lrelu(kk.x + pk.x)*is.x, lrelu(kk.y + pk.y)*is.y,
                        lrelu(kk.z + pk.z)*is.z, lrelu(kk.w + pk.w)*is.w };
        #pragma unroll
        for (int j = 0; j < 4; j++){
            float t2 = ta[j]*ta[j]; float t3 = t2*ta[j];
            s2q += t2; s6q += t3*t3; tq3[i*4+j] = t3;
            float u2 = tb[j]*tb[j]; float u3 = u2*tb[j];
            s2k += u2; s6k += u3*u3; tk3[i*4+j] = u3;
        }
    }
    #pragma unroll
    for (int off = 16; off; off >>= 1){
        s2q += __shfl_xor_sync(0xffffffffu, s2q, off);
        s6q += __shfl_xor_sync(0xffffffffu, s6q, off);
        s2k += __shfl_xor_sync(0xffffffffu, s2k, off);
        s6k += __shfl_xor_sync(0xffffffffu, s6k, off);
    }
    float rq = sqrtf(s2q / s6q);
    float rk = sqrtf(s2k / s6k);
    #pragma unroll
    for (int i = 0; i < 4; i++){
        int c = i*128 + lane*4;
        *(float4*)&g_Q[(b*NN + n)*CC + c] =
            make_float4(rq*tq3[i*4], rq*tq3[i*4+1], rq*tq3[i*4+2], rq*tq3[i*4+3]);
        *(float4*)&g_K[(b*NN + n)*CC + c] =
            make_float4(rk*tk3[i*4], rk*tk3[i*4+1], rk*tk3[i*4+2], rk*tk3[i*4+3]);
    }
}

// ---------------- K4: kv[b,h,d,e] = (1/N) sum_n k*v ----------------
__global__ void __launch_bounds__(256) k_kv(){
    __shared__ float ks[64][HD];
    __shared__ float vs[64][HD];
    __shared__ float red[256*16];
    int bh = blockIdx.x;
    int b = bh >> 4, h = bh & 15;
    int tid = threadIdx.x;
    int g  = tid >> 6;
    int t6 = tid & 63;
    int ty = t6 >> 3, tx = t6 & 7;
    float acc[4][4] = {};
    const float* Kb = &g_K [(b*NN)*CC + h*HD];
    const float* Vb = &g_P2[(b*NN)*CC + h*HD];
    for (int ch = 0; ch < 64; ch++){
        #pragma unroll
        for (int p = 0; p < 8; p++){
            int l = p*256 + tid;
            int d = l & 31, nn = l >> 5;
            ks[nn][d] = Kb[(ch*64 + nn)*CC + d];
            vs[nn][d] = Vb[(ch*64 + nn)*CC + d];
        }
        __syncthreads();
        #pragma unroll
        for (int q = 0; q < 16; q++){
            int n = g*16 + q;
            float4 kk = *(const float4*)&ks[n][ty*4];
            float4 vv = *(const float4*)&vs[n][tx*4];
            float ka[4] = {kk.x, kk.y, kk.z, kk.w};
            float va[4] = {vv.x, vv.y, vv.z, vv.w};
            #pragma unroll
            for (int i = 0; i < 4; i++)
                #pragma unroll
                for (int j = 0; j < 4; j++) acc[i][j] += ka[i]*va[j];
        }
        __syncthreads();
    }
    #pragma unroll
    for (int i = 0; i < 4; i++)
        #pragma unroll
        for (int j = 0; j < 4; j++) red[tid*16 + i*4 + j] = acc[i][j];
    __syncthreads();
    if (tid < 64){
        #pragma unroll
        for (int idx = 0; idx < 16; idx++){
            float s = red[tid*16 + idx] + red[(tid+64)*16 + idx]
                    + red[(tid+128)*16 + idx] + red[(tid+192)*16 + idx];
            int i = idx >> 2, j = idx & 3;
            int d = (tid >> 3)*4 + i, e = (tid & 7)*4 + j;
            g_KV[(bh*HD + d)*HD + e] = s * (1.0f/NN);
        }
    }
}

// ---------------- K5: attn = q@kv + lrelu(v@wv^T + bv) -> (B,C,N) ----------------
__global__ void __launch_bounds__(256) k_attn(const float* __restrict__ w_v,
                                              const float* __restrict__ b_v){
    __shared__ float qs [128][HD];
    __shared__ float vsm[128][HD];
    __shared__ float osm[HD][128];
    int bh = blockIdx.x, seg = blockIdx.y;
    int b = bh >> 4, h = bh & 15;
    int tid = threadIdx.x;
    int e = tid & 31, grp = tid >> 5;
    float kvc[32], wv[32];
    #pragma unroll
    for (int d = 0; d < 32; d++){
        kvc[d] = g_KV[(bh*HD + d)*HD + e];   // kv[:,e]
        wv[d]  = w_v[e*HD + d];
    }
    float bve = b_v[e];
    const float* Qb = &g_Q [(b*NN)*CC + h*HD];
    const float* Vb = &g_P2[(b*NN)*CC + h*HD];
    float* Ob = &g_ATT[(b*CC + h*HD)*NN];
    for (int cc = 0; cc < 8; cc++){
        int n0 = seg*1024 + cc*128;
        #pragma unroll
        for (int p = 0; p < 16; p++){
            int l = p*256 + tid;
            int d = l & 31, nn = l >> 5;
            qs [nn][d] = Qb[(n0 + nn)*CC + d];
            vsm[nn][d] = Vb[(n0 + nn)*CC + d];
        }
        __syncthreads();
        #pragma unroll
        for (int q = 0; q < 16; q++){
            int nn = grp*16 + q;
            float x = 0.f, vc = 0.f;
            #pragma unroll
            for (int d = 0; d < 32; d++){
                x  += qs [nn][d] * kvc[d];
                vc += vsm[nn][d] * wv[d];
            }
            osm[e][nn] = x + lrelu(vc + bve);
        }
        __syncthreads();
        #pragma unroll
        for (int p = 0; p < 16; p++){
            int l = p*256 + tid;
            int nn = l & 127, ee = l >> 7;
            Ob[ee*NN + n0 + nn] = osm[ee][nn];
        }
        __syncthreads();
    }
}

// ---------------- K6: bilinear upsample 64->128 + sigmoid ----------------
__global__ void __launch_bounds__(256) k_upsample(float* __restrict__ out){
    int x  = threadIdx.x & 127, ys = threadIdx.x >> 7;
    int y  = blockIdx.x*2 + ys;
    int c  = blockIdx.y, b = blockIdx.z;
    const float S = 63.f / 127.f;
    float tyf = (float)y * S; int y0 = (int)tyf; if (y0 > 62) y0 = 62; float wy = tyf - (float)y0;
    float txf = (float)x * S; int x0 = (int)txf; if (x0 > 62) x0 = 62; float wx = txf - (float)x0;
    const float* att = &g_ATT[(b*CC + c)*NN];
    float a00 = att[y0*64 + x0    ], a01 = att[y0*64 + x0 + 1];
    float a10 = att[(y0+1)*64 + x0], a11 = att[(y0+1)*64 + x0 + 1];
    float r0 = a00*(1.f - wx) + a01*wx;
    float r1 = a10*(1.f - wx) + a11*wx;
    float v  = r0*(1.f - wy) + r1*wy;
    out[((b*CC + c)*HW + y)*HW + x] = 1.f / (1.f + expf(-v));
}

// ---------------- launch ----------------
extern "C" void kernel_launch(void* const* d_in, const int* in_sizes, int n_in,
                              void* d_out, int out_size){
    const float* input1 = (const float*)d_in[0];
    const float* input2 = (const float*)d_in[1];
    const float* w_in   = (const float*)d_in[2];
    const float* b_in   = (const float*)d_in[3];
    const float* w_v    = (const float*)d_in[4];
    const float* b_v    = (const float*)d_in[5];
    const float* sparam = (const float*)d_in[6];
    const float* pos1   = (const float*)d_in[7];
    const float* pos2   = (const float*)d_in[8];
    float* out = (float*)d_out;

    k_scale    <<<1, CC>>>(sparam);
    k_pool1    <<<dim3(64, 8, 8), 256>>>(input1);
    k_gemm_pool<<<dim3(128, 4, 8), 256>>>(input2, w_in, b_in);
    k_focus    <<<4096, 256>>>(pos1, pos2);
    k_kv       <<<128, 256>>>();
    k_attn     <<<dim3(128, 4), 256>>>(w_v, b_v);
    k_upsample <<<dim3(64, 512, 8), 256>>>(out);
}

// round 4
// speedup vs baseline: 1.0023x; 1.0023x over previous
#include <cuda_runtime.h>
#include <math.h>

#define BB   8
#define CC   512
#define CIN  256
#define HW   128
#define NN   4096
#define NHD  16
#define HD   32

// ---------------- scratch (__device__ globals: allocation-free) ----------------
__device__ float g_P1 [BB*NN*CC];   // pooled input1, (B,N,C)
__device__ float g_P2 [BB*NN*CC];   // pooled transformed input2 (= v), (B,N,C)
__device__ float g_Q  [BB*NN*CC];   // focused q, (B,N,C)
__device__ float g_K  [BB*NN*CC];   // focused k, (B,N,C)
__device__ float g_KV [BB*NHD*HD*HD];
__device__ float g_ATT[BB*CC*NN];   // attn pre-upsample, (B,C,N)
__device__ float g_isc[CC];         // 1/softplus(scale_param)

// ---------------- helpers ----------------
__device__ __forceinline__ float lrelu(float x){ return x >= 0.f ? x : 0.1f*x; }

__device__ __forceinline__ unsigned long long ffma2(unsigned long long a,
                                                    unsigned long long b,
                                                    unsigned long long c){
    unsigned long long d;
    asm("fma.rn.f32x2 %0, %1, %2, %3;" : "=l"(d) : "l"(a), "l"(b), "l"(c));
    return d;
}
__device__ __forceinline__ unsigned long long pack2(float x, float y){
    unsigned long long r; asm("mov.b64 %0, {%1,%2};" : "=l"(r) : "f"(x), "f"(y)); return r;
}
__device__ __forceinline__ void unpack2(unsigned long long v, float &x, float &y){
    asm("mov.b64 {%0,%1}, %2;" : "=f"(x), "=f"(y) : "l"(v));
}

// ---------------- K0: inverse softplus scale ----------------
__global__ void k_scale(const float* __restrict__ sp){
    int c = threadIdx.x;
    float s = sp[c];
    float v = (s > 20.f) ? s : log1pf(expf(s));
    g_isc[c] = 1.f / v;
}

// ---------------- K1: 2x2 max+mean pool of input1 -> (B,N,C) ----------------
__global__ void __launch_bounds__(256) k_pool1(const float* __restrict__ in1){
    __shared__ float tile[64][65];
    int ny = blockIdx.x, c0 = blockIdx.y * 64, b = blockIdx.z;
    int tid = threadIdx.x;
    #pragma unroll
    for (int p = 0; p < 16; p++){
        int l = p*256 + tid;
        int nx = l & 63, cc = l >> 6;
        const float* base = in1 + (((b*CC + c0+cc)*HW + 2*ny)*HW + 2*nx);
        float2 r0 = *(const float2*)base;
        float2 r1 = *(const float2*)(base + HW);
        float m = fmaxf(fmaxf(r0.x, r0.y), fmaxf(r1.x, r1.y));
        float s = (r0.x + r0.y + r1.x + r1.y) * 0.25f;
        tile[cc][nx] = m + s;
    }
    __syncthreads();
    #pragma unroll
    for (int p = 0; p < 16; p++){
        int l = p*256 + tid;
        int c = l & 63, nx = l >> 6;
        g_P1[(b*NN + ny*64 + nx)*CC + c0 + c] = tile[c][nx];
    }
}

// ---------------- K2: fused w_in GEMM + bias + 2x2 pool -> (B,N,C) ----------------
// M=128 o x 128 pixels per block, K=256, f32x2 packed FMA (FFMA2).
// B-tile columns are permuted so each pooled pixel's 4 sub-pixels are adjacent.
__global__ void __launch_bounds__(256) k_gemm_pool(const float* __restrict__ in2,
                                                  const float* __restrict__ w_in,
                                                  const float* __restrict__ b_in){
    __shared__ float As[32][132];   // As[k][o]
    __shared__ float Bs[32][128];   // Bs[k][px*4 + sy*2 + sx]
    __shared__ float bias[128];
    int pt = blockIdx.x;            // 0..127 : 32 pooled pixels each
    int o0 = blockIdx.y * 128;
    int b  = blockIdx.z;
    int n0 = pt * 32;
    int ny = n0 >> 6;
    int nx0 = n0 & 63;
    int tid = threadIdx.x;
    int tx = tid & 15, ty = tid >> 4;

    if (tid < 128) bias[tid] = b_in[o0 + tid];

    unsigned long long acc[4][8];   // [o-pair][pixel col] packed f32x2 over o
    #pragma unroll
    for (int i = 0; i < 4; i++)
        #pragma unroll
        for (int j = 0; j < 8; j++) acc[i][j] = 0ull;

    for (int kt = 0; kt < 8; kt++){
        int kbase = kt * 32;
        #pragma unroll
        for (int p = 0; p < 8; p++){            // A: 128 o x 32 k (transposed store)
            int l = p*256 + tid;
            int kk2 = l & 15, o = l >> 4;
            float2 w = *(const float2*)&w_in[(o0+o)*CIN + kbase + 2*kk2];
            As[2*kk2  ][o] = w.x;
            As[2*kk2+1][o] = w.y;
        }
        #pragma unroll
        for (int p = 0; p < 8; p++){            // B: 32 k x 128 pix (permuted)
            int l = p*256 + tid;
            int j2 = l & 31, sy = (l >> 5) & 1, k = l >> 6;
            float2 v = *(const float2*)&in2[((b*CIN + kbase + k)*HW + (2*ny + sy))*HW
                                            + 2*nx0 + 2*j2];
            Bs[k][j2*4 + sy*2    ] = v.x;
            Bs[k][j2*4 + sy*2 + 1] = v.y;
        }
        __syncthreads();
        #pragma unroll
        for (int k = 0; k < 32; k++){
            unsigned long long a2[4];
            #pragma unroll
            for (int i = 0; i < 4; i++)
                a2[i] = *(const unsigned long long*)&As[k][ty*8 + 2*i];
            float4 bl = *(const float4*)&Bs[k][tx*8];
            float4 bh = *(const float4*)&Bs[k][tx*8 + 4];
            float bv[8] = {bl.x, bl.y, bl.z, bl.w, bh.x, bh.y, bh.z, bh.w};
            #pragma unroll
            for (int j = 0; j < 8; j++){
                unsigned long long bd = pack2(bv[j], bv[j]);
                #pragma unroll
                for (int i = 0; i < 4; i++) acc[i][j] = ffma2(a2[i], bd, acc[i][j]);
            }
        }
        __syncthreads();
    }
    // epilogue: +bias, pool 4 sub-pixels (max + mean), write float4s
    float res[2][8];
    #pragma unroll
    for (int i = 0; i < 4; i++){
        float vlo[8], vhi[8];
        #pragma unroll
        for (int j = 0; j < 8; j++) unpack2(acc[i][j], vlo[j], vhi[j]);
        float blo = bias[ty*8 + 2*i], bhi = bias[ty*8 + 2*i + 1];
        #pragma unroll
        for (int g = 0; g < 2; g++){
            float m0 = -3.0e38f, s0 = 0.f, m1 = -3.0e38f, s1 = 0.f;
            #pragma unroll
            for (int s = 0; s < 4; s++){
                float t0 = vlo[g*4+s] + blo;
                float t1 = vhi[g*4+s] + bhi;
                m0 = fmaxf(m0, t0); s0 += t0;
                m1 = fmaxf(m1, t1); s1 += t1;
            }
            res[g][2*i  ] = m0 + 0.25f*s0;
            res[g][2*i+1] = m1 + 0.25f*s1;
        }
    }
    #pragma unroll
    for (int g = 0; g < 2; g++){
        float* dst = &g_P2[(b*NN + n0 + tx*2 + g)*CC + o0 + ty*8];
        *(float4*)(dst    ) = make_float4(res[g][0], res[g][1], res[g][2], res[g][3]);
        *(float4*)(dst + 4) = make_float4(res[g][4], res[g][5], res[g][6], res[g][7]);
    }
}

// ---------------- K3: q/k = focus(lrelu(p + pos) / scale), warp per row ----------------
__global__ void __launch_bounds__(256) k_focus(const float* __restrict__ pos1,
                                               const float* __restrict__ pos2){
    int warp = threadIdx.x >> 5, lane = threadIdx.x & 31;
    int r = blockIdx.x * 8 + warp;
    int b = r >> 12, n = r & (NN - 1);
    const float* p1 = &g_P1[(b*NN + n)*CC];
    const float* p2 = &g_P2[(b*NN + n)*CC];
    const float* q1 = &pos1[n*CC];
    const float* q2 = &pos2[n*CC];
    float tq3[16], tk3[16];
    float s2q = 0.f, s6q = 0.f, s2k = 0.f, s6k = 0.f;
    #pragma unroll
    for (int i = 0; i < 4; i++){
        int c = i*128 + lane*4;
        float4 a  = *(const float4*)(p1 + c);
        float4 pa = *(const float4*)(q1 + c);
        float4 kk = *(const float4*)(p2 + c);
        float4 pk = *(const float4*)(q2 + c);
        float4 is = *(const float4*)(g_isc + c);
        float ta[4] = { lrelu(a.x + pa.x)*is.x, lrelu(a.y + pa.y)*is.y,
                        lrelu(a.z + pa.z)*is.z, lrelu(a.w + pa.w)*is.w };
        float tb[4] = { lrelu(kk.x + pk.x)*is.x, lrelu(kk.y + pk.y)*is.y,
                        lrelu(kk.z + pk.z)*is.z, lrelu(kk.w + pk.w)*is.w };
        #pragma unroll
        for (int j = 0; j < 4; j++){
            float t2 = ta[j]*ta[j]; float t3 = t2*ta[j];
            s2q += t2; s6q += t3*t3; tq3[i*4+j] = t3;
            float u2 = tb[j]*tb[j]; float u3 = u2*tb[j];
            s2k += u2; s6k += u3*u3; tk3[i*4+j] = u3;
        }
    }
    #pragma unroll
    for (int off = 16; off; off >>= 1){
        s2q += __shfl_xor_sync(0xffffffffu, s2q, off);
        s6q += __shfl_xor_sync(0xffffffffu, s6q, off);
        s2k += __shfl_xor_sync(0xffffffffu, s2k, off);
        s6k += __shfl_xor_sync(0xffffffffu, s6k, off);
    }
    float rq = sqrtf(s2q / s6q);
    float rk = sqrtf(s2k / s6k);
    #pragma unroll
    for (int i = 0; i < 4; i++){
        int c = i*128 + lane*4;
        *(float4*)&g_Q[(b*NN + n)*CC + c] =
            make_float4(rq*tq3[i*4], rq*tq3[i*4+1], rq*tq3[i*4+2], rq*tq3[i*4+3]);
        *(float4*)&g_K[(b*NN + n)*CC + c] =
            make_float4(rk*tk3[i*4], rk*tk3[i*4+1], rk*tk3[i*4+2], rk*tk3[i*4+3]);
    }
}

// ---------------- K4: kv[b,h,d,e] = (1/N) sum_n k*v ----------------
__global__ void __launch_bounds__(256) k_kv(){
    __shared__ float ks[64][HD];
    __shared__ float vs[64][HD];
    __shared__ float red[256*16];
    int bh = blockIdx.x;
    int b = bh >> 4, h = bh & 15;
    int tid = threadIdx.x;
    int g  = tid >> 6;
    int t6 = tid & 63;
    int ty = t6 >> 3, tx = t6 & 7;
    float acc[4][4] = {};
    const float* Kb = &g_K [(b*NN)*CC + h*HD];
    const float* Vb = &g_P2[(b*NN)*CC + h*HD];
    for (int ch = 0; ch < 64; ch++){
        #pragma unroll
        for (int p = 0; p < 8; p++){
            int l = p*256 + tid;
            int d = l & 31, nn = l >> 5;
            ks[nn][d] = Kb[(ch*64 + nn)*CC + d];
            vs[nn][d] = Vb[(ch*64 + nn)*CC + d];
        }
        __syncthreads();
        #pragma unroll
        for (int q = 0; q < 16; q++){
            int n = g*16 + q;
            float4 kk = *(const float4*)&ks[n][ty*4];
            float4 vv = *(const float4*)&vs[n][tx*4];
            float ka[4] = {kk.x, kk.y, kk.z, kk.w};
            float va[4] = {vv.x, vv.y, vv.z, vv.w};
            #pragma unroll
            for (int i = 0; i < 4; i++)
                #pragma unroll
                for (int j = 0; j < 4; j++) acc[i][j] += ka[i]*va[j];
        }
        __syncthreads();
    }
    #pragma unroll
    for (int i = 0; i < 4; i++)
        #pragma unroll
        for (int j = 0; j < 4; j++) red[tid*16 + i*4 + j] = acc[i][j];
    __syncthreads();
    if (tid < 64){
        #pragma unroll
        for (int idx = 0; idx < 16; idx++){
            float s = red[tid*16 + idx] + red[(tid+64)*16 + idx]
                    + red[(tid+128)*16 + idx] + red[(tid+192)*16 + idx];
            int i = idx >> 2, j = idx & 3;
            int d = (tid >> 3)*4 + i, e = (tid & 7)*4 + j;
            g_KV[(bh*HD + d)*HD + e] = s * (1.0f/NN);
        }
    }
}

// ---------------- K5: attn = q@kv + lrelu(v@wv^T + bv) -> (B,C,N) ----------------
__global__ void __launch_bounds__(256) k_attn(const float* __restrict__ w_v,
                                              const float* __restrict__ b_v){
    __shared__ float qs [128][HD];
    __shared__ float vsm[128][HD];
    __shared__ float osm[HD][128];
    int bh = blockIdx.x, seg = blockIdx.y;
    int b = bh >> 4, h = bh & 15;
    int tid = threadIdx.x;
    int e = tid & 31, grp = tid >> 5;
    float kvc[32], wv[32];
    #pragma unroll
    for (int d = 0; d < 32; d++){
        kvc[d] = g_KV[(bh*HD + d)*HD + e];   // kv[:,e]
        wv[d]  = w_v[e*HD + d];
    }
    float bve = b_v[e];
    const float* Qb = &g_Q [(b*NN)*CC + h*HD];
    const float* Vb = &g_P2[(b*NN)*CC + h*HD];
    float* Ob = &g_ATT[(b*CC + h*HD)*NN];
    for (int cc = 0; cc < 8; cc++){
        int n0 = seg*1024 + cc*128;
        #pragma unroll
        for (int p = 0; p < 16; p++){
            int l = p*256 + tid;
            int d = l & 31, nn = l >> 5;
            qs [nn][d] = Qb[(n0 + nn)*CC + d];
            vsm[nn][d] = Vb[(n0 + nn)*CC + d];
        }
        __syncthreads();
        #pragma unroll
        for (int q = 0; q < 16; q++){
            int nn = grp*16 + q;
            float x = 0.f, vc = 0.f;
            #pragma unroll
            for (int d = 0; d < 32; d++){
                x  += qs [nn][d] * kvc[d];
                vc += vsm[nn][d] * wv[d];
            }
            osm[e][nn] = x + lrelu(vc + bve);
        }
        __syncthreads();
        #pragma unroll
        for (int p = 0; p < 16; p++){
            int l = p*256 + tid;
            int nn = l & 127, ee = l >> 7;
            Ob[ee*NN + n0 + nn] = osm[ee][nn];
        }
        __syncthreads();
    }
}

// ---------------- K6: bilinear upsample 64->128 + sigmoid ----------------
__global__ void __launch_bounds__(256) k_upsample(float* __restrict__ out){
    int x  = threadIdx.x & 127, ys = threadIdx.x >> 7;
    int y  = blockIdx.x*2 + ys;
    int c  = blockIdx.y, b = blockIdx.z;
    const float S = 63.f / 127.f;
    float tyf = (float)y * S; int y0 = (int)tyf; if (y0 > 62) y0 = 62; float wy = tyf - (float)y0;
    float txf = (float)x * S; int x0 = (int)txf; if (x0 > 62) x0 = 62; float wx = txf - (float)x0;
    const float* att = &g_ATT[(b*CC + c)*NN];
    float a00 = att[y0*64 + x0    ], a01 = att[y0*64 + x0 + 1];
    float a10 = att[(y0+1)*64 + x0], a11 = att[(y0+1)*64 + x0 + 1];
    float r0 = a00*(1.f - wx) + a01*wx;
    float r1 = a10*(1.f - wx) + a11*wx;
    float v  = r0*(1.f - wy) + r1*wy;
    out[((b*CC + c)*HW + y)*HW + x] = 1.f / (1.f + expf(-v));
}

// ---------------- launch ----------------
extern "C" void kernel_launch(void* const* d_in, const int* in_sizes, int n_in,
                              void* d_out, int out_size){
    const float* input1 = (const float*)d_in[0];
    const float* input2 = (const float*)d_in[1];
    const float* w_in   = (const float*)d_in[2];
    const float* b_in   = (const float*)d_in[3];
    const float* w_v    = (const float*)d_in[4];
    const float* b_v    = (const float*)d_in[5];
    const float* sparam = (const float*)d_in[6];
    const float* pos1   = (const float*)d_in[7];
    const float* pos2   = (const float*)d_in[8];
    float* out = (float*)d_out;

    k_scale    <<<1, CC>>>(sparam);
    k_pool1    <<<dim3(64, 8, 8), 256>>>(input1);
    k_gemm_pool<<<dim3(128, 4, 8), 256>>>(input2, w_in, b_in);
    k_focus    <<<4096, 256>>>(pos1, pos2);
    k_kv       <<<128, 256>>>();
    k_attn     <<<dim3(128, 4), 256>>>(w_v, b_v);
    k_upsample <<<dim3(64, 512, 8), 256>>>(out);
}

// round 8
// speedup vs baseline: 1.3617x; 1.3586x over previous
#include <cuda_runtime.h>
#include <cuda_bf16.h>
#include <stdint.h>
#include <math.h>

#define BB   8
#define CC   512
#define CIN  256
#define HW   128
#define NN   4096
#define NHD  16
#define HD   32

__device__ float g_P1 [BB*NN*CC];
__device__ float g_P2 [BB*NN*CC];
__device__ float g_Q  [BB*NN*CC];
__device__ float g_K  [BB*NN*CC];
__device__ float g_KV [BB*NHD*HD*HD];
__device__ float g_ATT[BB*CC*NN];
__device__ float g_isc[CC];
__device__ __nv_bfloat16 g_2h[BB*CIN*HW*HW];
__device__ __nv_bfloat16 g_2l[BB*CIN*HW*HW];
__device__ __nv_bfloat16 g_wh[CC*CIN];
__device__ __nv_bfloat16 g_wl[CC*CIN];

__device__ __forceinline__ float lrelu(float x){ return x >= 0.f ? x : 0.1f*x; }

__device__ __forceinline__ uint32_t smem_u32(const void* p){
    uint32_t a;
    asm("{ .reg .u64 t; cvta.to.shared.u64 t, %1; cvt.u32.u64 %0, t; }" : "=r"(a) : "l"(p));
    return a;
}
__device__ __forceinline__ void cp16(uint32_t dst, const void* src){
    asm volatile("cp.async.cg.shared.global [%0], [%1], 16;" :: "r"(dst), "l"(src) : "memory");
}
#define CP_COMMIT()  asm volatile("cp.async.commit_group;" ::: "memory")
#define CP_WAIT_ALL() asm volatile("cp.async.wait_group 0;" ::: "memory")

__device__ __forceinline__ void ldsm4(uint32_t* r, uint32_t addr){
    asm volatile("ldmatrix.sync.aligned.m8n8.x4.shared.b16 {%0,%1,%2,%3}, [%4];"
        : "=r"(r[0]), "=r"(r[1]), "=r"(r[2]), "=r"(r[3]) : "r"(addr));
}
__device__ __forceinline__ void ldsm4t(uint32_t* r, uint32_t addr){
    asm volatile("ldmatrix.sync.aligned.m8n8.x4.trans.shared.b16 {%0,%1,%2,%3}, [%4];"
        : "=r"(r[0]), "=r"(r[1]), "=r"(r[2]), "=r"(r[3]) : "r"(addr));
}
__device__ __forceinline__ void mma16816(float* d, const uint32_t* a, const uint32_t* b){
    asm volatile("mma.sync.aligned.m16n8k16.row.col.f32.bf16.bf16.f32 "
        "{%0,%1,%2,%3}, {%4,%5,%6,%7}, {%8,%9}, {%0,%1,%2,%3};"
        : "+f"(d[0]), "+f"(d[1]), "+f"(d[2]), "+f"(d[3])
        : "r"(a[0]), "r"(a[1]), "r"(a[2]), "r"(a[3]), "r"(b[0]), "r"(b[1]));
}

// ---------------- K0: inverse softplus scale ----------------
__global__ void k_scale(const float* __restrict__ sp){
    int c = threadIdx.x;
    float s = sp[c];
    float v = (s > 20.f) ? s : log1pf(expf(s));
    g_isc[c] = 1.f / v;
}

// ---------------- K0b/K0c: bf16 hi/lo splits ----------------
__device__ __forceinline__ void split4(float4 v, __nv_bfloat162* H, __nv_bfloat162* L, int i){
    __nv_bfloat16 h0 = __float2bfloat16(v.x), h1 = __float2bfloat16(v.y);
    __nv_bfloat16 h2 = __float2bfloat16(v.z), h3 = __float2bfloat16(v.w);
    __nv_bfloat162 H0; H0.x = h0; H0.y = h1;
    __nv_bfloat162 H1; H1.x = h2; H1.y = h3;
    __nv_bfloat162 L0, L1;
    L0.x = __float2bfloat16(v.x - __bfloat162float(h0));
    L0.y = __float2bfloat16(v.y - __bfloat162float(h1));
    L1.x = __float2bfloat16(v.z - __bfloat162float(h2));
    L1.y = __float2bfloat16(v.w - __bfloat162float(h3));
    H[2*i] = H0; H[2*i+1] = H1; L[2*i] = L0; L[2*i+1] = L1;
}
__global__ void __launch_bounds__(256) k_split(const float* __restrict__ in2){
    int i = blockIdx.x*256 + threadIdx.x;
    split4(((const float4*)in2)[i], (__nv_bfloat162*)g_2h, (__nv_bfloat162*)g_2l, i);
}
__global__ void __launch_bounds__(256) k_splitw(const float* __restrict__ w){
    int i = blockIdx.x*256 + threadIdx.x;
    split4(((const float4*)w)[i], (__nv_bfloat162*)g_wh, (__nv_bfloat162*)g_wl, i);
}

// ---------------- K1: 2x2 max+mean pool of input1 -> (B,N,C) ----------------
__global__ void __launch_bounds__(256) k_pool1(const float* __restrict__ in1){
    __shared__ float tile[64][65];
    int ny = blockIdx.x, c0 = blockIdx.y * 64, b = blockIdx.z;
    int tid = threadIdx.x;
    #pragma unroll
    for (int p = 0; p < 16; p++){
        int l = p*256 + tid;
        int nx = l & 63, cc = l >> 6;
        const float* base = in1 + (((b*CC + c0+cc)*HW + 2*ny)*HW + 2*nx);
        float2 r0 = *(const float2*)base;
        float2 r1 = *(const float2*)(base + HW);
        float m = fmaxf(fmaxf(r0.x, r0.y), fmaxf(r1.x, r1.y));
        float s = (r0.x + r0.y + r1.x + r1.y) * 0.25f;
        tile[cc][nx] = m + s;
    }
    __syncthreads();
    #pragma unroll
    for (int p = 0; p < 16; p++){
        int l = p*256 + tid;
        int c = l & 63, nx = l >> 6;
        g_P1[(b*NN + ny*64 + nx)*CC + c0 + c] = tile[c][nx];
    }
}

// ---------------- K2: mma.sync bf16-split GEMM + bias + 2x2 pool -> g_P2 ----------------
// CTA: 128 o x 128 px (2 y-rows x 64 x). K=256, k32 stages, double buffered.
// 3-term split: Ah*Bh + Al*Bh + Ah*Bl.
// smem stage (32KB): A[split][o(128)][k(32)] 64B rows, chunk^((o>>1)&3)
//                    B[split][k(32)][n(128)] 256B rows, chunk^(k&7)
// C staging reuses stage memory: 128 x 132 f32.
#define STAGE_SZ 32768
#define GEMM_SMEM (128*132*4)   // 67584 >= 2*STAGE_SZ

__global__ void __launch_bounds__(256, 1) k_gemm(const float* __restrict__ b_in){
    extern __shared__ char smem[];
    uint32_t sb = smem_u32(smem);
    float* Cs = (float*)smem;

    int tid = threadIdx.x;
    int lane = tid & 31, wid = tid >> 5;
    int wm = wid >> 2, wn = wid & 3;           // 2 x 4 warps
    int pt = blockIdx.x;                        // 0..127
    int o0 = blockIdx.y * 128;
    int b  = blockIdx.z;
    int ny = pt >> 1, xh = pt & 1;

    const __nv_bfloat16* Bsrc[2] = { g_2h, g_2l };
    const __nv_bfloat16* Asrc[2] = { g_wh, g_wl };

    float acc[4][4][4];
    #pragma unroll
    for (int i = 0; i < 4; i++)
        #pragma unroll
        for (int j = 0; j < 4; j++)
            #pragma unroll
            for (int q = 0; q < 4; q++) acc[i][j][q] = 0.f;

    // ---- stage loader ----
    auto load_stage = [&](int kc){
        uint32_t st = sb + (kc & 1)*STAGE_SZ;
        #pragma unroll
        for (int q = 0; q < 4; q++){            // A: 1024 chunks
            int id = q*256 + tid;
            int sp = id >> 9, o = (id >> 2) & 127, c = id & 3;
            int cs = c ^ ((o >> 1) & 3);
            const __nv_bfloat16* src = Asrc[sp] + (o0 + o)*CIN + kc*32 + c*8;
            cp16(st + sp*8192 + o*64 + cs*16, src);
        }
        #pragma unroll
        for (int q = 0; q < 4; q++){            // B: 1024 chunks
            int id = q*256 + tid;
            int sp = id >> 9, k = (id >> 4) & 31, c = id & 15;
            int cs = c ^ (k & 7);
            int sy = c >> 3, nx0 = (c & 7) << 3;
            const __nv_bfloat16* src = Bsrc[sp]
                + (size_t)(b*CIN + kc*32 + k)*(HW*HW) + (2*ny + sy)*HW + xh*64 + nx0;
            cp16(st + 16384 + sp*8192 + k*256 + cs*16, src);
        }
        CP_COMMIT();
    };

    load_stage(0);
    int l15 = lane & 15, lh = lane >> 4;
    int g2 = lane >> 3;
    int bk_off = (g2 & 1)*8 + (lane & 7);       // k within k16 for B ldmatrix lane
    int bn_off = (g2 >> 1)*8;                   // n offset for B ldmatrix lane

    for (int kc = 0; kc < 8; kc++){
        CP_WAIT_ALL();
        __syncthreads();
        if (kc < 7) load_stage(kc + 1);
        uint32_t st = sb + (kc & 1)*STAGE_SZ;

        #pragma unroll
        for (int ks = 0; ks < 2; ks++){
            uint32_t Ah[4][4], Al[4][4];
            #pragma unroll
            for (int mf = 0; mf < 4; mf++){
                int r = wm*64 + mf*16 + l15;
                int c = ks*2 + lh;
                int cs = c ^ ((r >> 1) & 3);
                uint32_t base = st + r*64 + cs*16;
                ldsm4(Ah[mf], base);
                ldsm4(Al[mf], base + 8192);
            }
            uint32_t Bh[2][4], Bl[2][4];
            #pragma unroll
            for (int nf2 = 0; nf2 < 2; nf2++){
                int k = ks*16 + bk_off;
                int n = wn*32 + nf2*16 + bn_off;
                int c = n >> 3;
                int cs = c ^ (k & 7);
                uint32_t base = st + 16384 + k*256 + cs*16;
                ldsm4t(Bh[nf2], base);
                ldsm4t(Bl[nf2], base + 8192);
            }
            #pragma unroll
            for (int mf = 0; mf < 4; mf++)
                #pragma unroll
                for (int nf = 0; nf < 4; nf++){
                    const uint32_t* bh = &Bh[nf >> 1][(nf & 1)*2];
                    const uint32_t* bl = &Bl[nf >> 1][(nf & 1)*2];
                    mma16816(acc[mf][nf], Ah[mf], bh);
                    mma16816(acc[mf][nf], Al[mf], bh);
                    mma16816(acc[mf][nf], Ah[mf], bl);
                }
        }
        __syncthreads();
    }

    // ---- epilogue: stage C in smem, pool 2x2 (max + mean), +2*bias ----
    #pragma unroll
    for (int mf = 0; mf < 4; mf++)
        #pragma unroll
        for (int nf = 0; nf < 4; nf++){
            int row = wm*64 + mf*16 + (lane >> 2);
            int col = wn*32 + nf*8 + (lane & 3)*2;
            *(float2*)&Cs[row*132 + col]       = make_float2(acc[mf][nf][0], acc[mf][nf][1]);
            *(float2*)&Cs[(row+8)*132 + col]   = make_float2(acc[mf][nf][2], acc[mf][nf][3]);
        }
    __syncthreads();

    int pn_base = b*NN + ny*64 + xh*32;
    #pragma unroll
    for (int j = 0; j < 16; j++){
        int idx = j*256 + tid;
        int o = idx & 127, i = idx >> 7;        // o 0..127, pooled px i 0..31
        float2 v0 = *(const float2*)&Cs[o*132 + 2*i];
        float2 v1 = *(const float2*)&Cs[o*132 + 64 + 2*i];
        float m = fmaxf(fmaxf(v0.x, v0.y), fmaxf(v1.x, v1.y));
        float s = (v0.x + v0.y + v1.x + v1.y) * 0.25f;
        g_P2[(pn_base + i)*CC + o0 + o] = m + s + 2.f*b_in[o0 + o];
    }
}

// ---------------- K3: q/k = focus(lrelu(p + pos) / scale) ----------------
__global__ void __launch_bounds__(256) k_focus(const float* __restrict__ pos1,
                                               const float* __restrict__ pos2){
    int warp = threadIdx.x >> 5, lane = threadIdx.x & 31;
    int r = blockIdx.x * 8 + warp;
    int b = r >> 12, n = r & (NN - 1);
    const float* p1 = &g_P1[(b*NN + n)*CC];
    const float* p2 = &g_P2[(b*NN + n)*CC];
    const float* q1 = &pos1[n*CC];
    const float* q2 = &pos2[n*CC];
    float tq3[16], tk3[16];
    float s2q = 0.f, s6q = 0.f, s2k = 0.f, s6k = 0.f;
    #pragma unroll
    for (int i = 0; i < 4; i++){
        int c = i*128 + lane*4;
        float4 a  = *(const float4*)(p1 + c);
        float4 pa = *(const float4*)(q1 + c);
        float4 kk = *(const float4*)(p2 + c);
        float4 pk = *(const float4*)(q2 + c);
        float4 is = *(const float4*)(g_isc + c);
        float ta[4] = { lrelu(a.x + pa.x)*is.x, lrelu(a.y + pa.y)*is.y,
                        lrelu(a.z + pa.z)*is.z, lrelu(a.w + pa.w)*is.w };
        float tb[4] = { lrelu(kk.x + pk.x)*is.x, lrelu(kk.y + pk.y)*is.y,
                        lrelu(kk.z + pk.z)*is.z, lrelu(kk.w + pk.w)*is.w };
        #pragma unroll
        for (int j = 0; j < 4; j++){
            float t2 = ta[j]*ta[j]; float t3 = t2*ta[j];
            s2q += t2; s6q += t3*t3; tq3[i*4+j] = t3;
            float u2 = tb[j]*tb[j]; float u3 = u2*tb[j];
            s2k += u2; s6k += u3*u3; tk3[i*4+j] = u3;
        }
    }
    #pragma unroll
    for (int off = 16; off; off >>= 1){
        s2q += __shfl_xor_sync(0xffffffffu, s2q, off);
        s6q += __shfl_xor_sync(0xffffffffu, s6q, off);
        s2k += __shfl_xor_sync(0xffffffffu, s2k, off);
        s6k += __shfl_xor_sync(0xffffffffu, s6k, off);
    }
    float rq = sqrtf(s2q / s6q);
    float rk = sqrtf(s2k / s6k);
    #pragma unroll
    for (int i = 0; i < 4; i++){
        int c = i*128 + lane*4;
        *(float4*)&g_Q[(b*NN + n)*CC + c] =
            make_float4(rq*tq3[i*4], rq*tq3[i*4+1], rq*tq3[i*4+2], rq*tq3[i*4+3]);
        *(float4*)&g_K[(b*NN + n)*CC + c] =
            make_float4(rk*tk3[i*4], rk*tk3[i*4+1], rk*tk3[i*4+2], rk*tk3[i*4+3]);
    }
}

// ---------------- K4: kv ----------------
__global__ void __launch_bounds__(256) k_kv(){
    __shared__ float ks[64][HD];
    __shared__ float vs[64][HD];
    __shared__ float red[256*16];
    int bh = blockIdx.x;
    int b = bh >> 4, h = bh & 15;
    int tid = threadIdx.x;
    int g  = tid >> 6;
    int t6 = tid & 63;
    int ty = t6 >> 3, tx = t6 & 7;
    float acc[4][4] = {};
    const float* Kb = &g_K [(b*NN)*CC + h*HD];
    const float* Vb = &g_P2[(b*NN)*CC + h*HD];
    for (int ch = 0; ch < 64; ch++){
        #pragma unroll
        for (int p = 0; p < 8; p++){
            int l = p*256 + tid;
            int d = l & 31, nn = l >> 5;
            ks[nn][d] = Kb[(ch*64 + nn)*CC + d];
            vs[nn][d] = Vb[(ch*64 + nn)*CC + d];
        }
        __syncthreads();
        #pragma unroll
        for (int q = 0; q < 16; q++){
            int n = g*16 + q;
            float4 kk = *(const float4*)&ks[n][ty*4];
            float4 vv = *(const float4*)&vs[n][tx*4];
            float ka[4] = {kk.x, kk.y, kk.z, kk.w};
            float va[4] = {vv.x, vv.y, vv.z, vv.w};
            #pragma unroll
            for (int i = 0; i < 4; i++)
                #pragma unroll
                for (int j = 0; j < 4; j++) acc[i][j] += ka[i]*va[j];
        }
        __syncthreads();
    }
    #pragma unroll
    for (int i = 0; i < 4; i++)
        #pragma unroll
        for (int j = 0; j < 4; j++) red[tid*16 + i*4 + j] = acc[i][j];
    __syncthreads();
    if (tid < 64){
        #pragma unroll
        for (int idx = 0; idx < 16; idx++){
            float s = red[tid*16 + idx] + red[(tid+64)*16 + idx]
                    + red[(tid+128)*16 + idx] + red[(tid+192)*16 + idx];
            int i = idx >> 2, j = idx & 3;
            int d = (tid >> 3)*4 + i, e = (tid & 7)*4 + j;
            g_KV[(bh*HD + d)*HD + e] = s * (1.0f/NN);
        }
    }
}

// ---------------- K5: attn ----------------
__global__ void __launch_bounds__(256) k_attn(const float* __restrict__ w_v,
                                              const float* __restrict__ b_v){
    __shared__ float qs [128][HD];
    __shared__ float vsm[128][HD];
    __shared__ float osm[HD][128];
    int bh = blockIdx.x, seg = blockIdx.y;
    int b = bh >> 4, h = bh & 15;
    int tid = threadIdx.x;
    int e = tid & 31, grp = tid >> 5;
    float kvc[32], wv[32];
    #pragma unroll
    for (int d = 0; d < 32; d++){
        kvc[d] = g_KV[(bh*HD + d)*HD + e];
        wv[d]  = w_v[e*HD + d];
    }
    float bve = b_v[e];
    const float* Qb = &g_Q [(b*NN)*CC + h*HD];
    const float* Vb = &g_P2[(b*NN)*CC + h*HD];
    float* Ob = &g_ATT[(b*CC + h*HD)*NN];
    for (int cc = 0; cc < 8; cc++){
        int n0 = seg*1024 + cc*128;
        #pragma unroll
        for (int p = 0; p < 16; p++){
            int l = p*256 + tid;
            int d = l & 31, nn = l >> 5;
            qs [nn][d] = Qb[(n0 + nn)*CC + d];
            vsm[nn][d] = Vb[(n0 + nn)*CC + d];
        }
        __syncthreads();
        #pragma unroll
        for (int q = 0; q < 16; q++){
            int nn = grp*16 + q;
            float x = 0.f, vc = 0.f;
            #pragma unroll
            for (int d = 0; d < 32; d++){
                x  += qs [nn][d] * kvc[d];
                vc += vsm[nn][d] * wv[d];
            }
            osm[e][nn] = x + lrelu(vc + bve);
        }
        __syncthreads();
        #pragma unroll
        for (int p = 0; p < 16; p++){
            int l = p*256 + tid;
            int nn = l & 127, ee = l >> 7;
            Ob[ee*NN + n0 + nn] = osm[ee][nn];
        }
        __syncthreads();
    }
}

// ---------------- K6: bilinear upsample + sigmoid ----------------
__global__ void __launch_bounds__(256) k_upsample(float* __restrict__ out){
    int x  = threadIdx.x & 127, ys = threadIdx.x >> 7;
    int y  = blockIdx.x*2 + ys;
    int c  = blockIdx.y, b = blockIdx.z;
    const float S = 63.f / 127.f;
    float tyf = (float)y * S; int y0 = (int)tyf; if (y0 > 62) y0 = 62; float wy = tyf - (float)y0;
    float txf = (float)x * S; int x0 = (int)txf; if (x0 > 62) x0 = 62; float wx = txf - (float)x0;
    const float* att = &g_ATT[(b*CC + c)*NN];
    float a00 = att[y0*64 + x0    ], a01 = att[y0*64 + x0 + 1];
    float a10 = att[(y0+1)*64 + x0], a11 = att[(y0+1)*64 + x0 + 1];
    float r0 = a00*(1.f - wx) + a01*wx;
    float r1 = a10*(1.f - wx) + a11*wx;
    float v  = r0*(1.f - wy) + r1*wy;
    out[((b*CC + c)*HW + y)*HW + x] = 1.f / (1.f + expf(-v));
}

// ---------------- launch ----------------
extern "C" void kernel_launch(void* const* d_in, const int* in_sizes, int n_in,
                              void* d_out, int out_size){
    const float* input1 = (const float*)d_in[0];
    const float* input2 = (const float*)d_in[1];
    const float* w_in   = (const float*)d_in[2];
    const float* b_in   = (const float*)d_in[3];
    const float* w_v    = (const float*)d_in[4];
    const float* b_v    = (const float*)d_in[5];
    const float* sparam = (const float*)d_in[6];
    const float* pos1   = (const float*)d_in[7];
    const float* pos2   = (const float*)d_in[8];
    float* out = (float*)d_out;

    cudaFuncSetAttribute(k_gemm, cudaFuncAttributeMaxDynamicSharedMemorySize, GEMM_SMEM);

    k_scale    <<<1, CC>>>(sparam);
    k_splitw   <<<128, 256>>>(w_in);
    k_split    <<<32768, 256>>>(input2);
    k_pool1    <<<dim3(64, 8, 8), 256>>>(input1);
    k_gemm     <<<dim3(128, 4, 8), 256, GEMM_SMEM>>>(b_in);
    k_focus    <<<4096, 256>>>(pos1, pos2);
    k_kv       <<<128, 256>>>();
    k_attn     <<<dim3(128, 4), 256>>>(w_v, b_v);
    k_upsample <<<dim3(64, 512, 8), 256>>>(out);
}

// round 9
// speedup vs baseline: 1.4565x; 1.0696x over previous
#include <cuda_runtime.h>
#include <cuda_bf16.h>
#include <stdint.h>
#include <math.h>

#define BB   8
#define CC   512
#define CIN  256
#define HW   128
#define NN   4096
#define NHD  16
#define HD   32

__device__ float g_P1 [BB*NN*CC];
__device__ float g_P2 [BB*NN*CC];
__device__ float g_Q  [BB*NN*CC];
__device__ float g_K  [BB*NN*CC];
__device__ float g_KV [BB*NHD*HD*HD];
__device__ float g_ATT[BB*CC*NN];
__device__ float g_isc[CC];
__device__ __nv_bfloat16 g_2h[BB*CIN*HW*HW];
__device__ __nv_bfloat16 g_2l[BB*CIN*HW*HW];
__device__ __nv_bfloat16 g_wh[CC*CIN];
__device__ __nv_bfloat16 g_wl[CC*CIN];

__device__ __forceinline__ float lrelu(float x){ return x >= 0.f ? x : 0.1f*x; }

__device__ __forceinline__ uint32_t smem_u32(const void* p){
    uint32_t a;
    asm("{ .reg .u64 t; cvta.to.shared.u64 t, %1; cvt.u32.u64 %0, t; }" : "=r"(a) : "l"(p));
    return a;
}
__device__ __forceinline__ void cp16(uint32_t dst, const void* src){
    asm volatile("cp.async.cg.shared.global [%0], [%1], 16;" :: "r"(dst), "l"(src) : "memory");
}
#define CP_COMMIT()   asm volatile("cp.async.commit_group;" ::: "memory")
#define CP_WAIT(n)    asm volatile("cp.async.wait_group %0;" :: "n"(n) : "memory")

__device__ __forceinline__ void ldsm4(uint32_t* r, uint32_t addr){
    asm volatile("ldmatrix.sync.aligned.m8n8.x4.shared.b16 {%0,%1,%2,%3}, [%4];"
        : "=r"(r[0]), "=r"(r[1]), "=r"(r[2]), "=r"(r[3]) : "r"(addr));
}
__device__ __forceinline__ void ldsm4t(uint32_t* r, uint32_t addr){
    asm volatile("ldmatrix.sync.aligned.m8n8.x4.trans.shared.b16 {%0,%1,%2,%3}, [%4];"
        : "=r"(r[0]), "=r"(r[1]), "=r"(r[2]), "=r"(r[3]) : "r"(addr));
}
__device__ __forceinline__ void mma16816(float* d, const uint32_t* a, const uint32_t* b){
    asm volatile("mma.sync.aligned.m16n8k16.row.col.f32.bf16.bf16.f32 "
        "{%0,%1,%2,%3}, {%4,%5,%6,%7}, {%8,%9}, {%0,%1,%2,%3};"
        : "+f"(d[0]), "+f"(d[1]), "+f"(d[2]), "+f"(d[3])
        : "r"(a[0]), "r"(a[1]), "r"(a[2]), "r"(a[3]), "r"(b[0]), "r"(b[1]));
}

// ---------------- K0: inverse softplus scale ----------------
__global__ void k_scale(const float* __restrict__ sp){
    int c = threadIdx.x;
    float s = sp[c];
    float v = (s > 20.f) ? s : log1pf(expf(s));
    g_isc[c] = 1.f / v;
}

// ---------------- K0b/K0c: bf16 hi/lo splits ----------------
__device__ __forceinline__ void split4(float4 v, __nv_bfloat162* H, __nv_bfloat162* L, int i){
    __nv_bfloat16 h0 = __float2bfloat16(v.x), h1 = __float2bfloat16(v.y);
    __nv_bfloat16 h2 = __float2bfloat16(v.z), h3 = __float2bfloat16(v.w);
    __nv_bfloat162 H0; H0.x = h0; H0.y = h1;
    __nv_bfloat162 H1; H1.x = h2; H1.y = h3;
    __nv_bfloat162 L0, L1;
    L0.x = __float2bfloat16(v.x - __bfloat162float(h0));
    L0.y = __float2bfloat16(v.y - __bfloat162float(h1));
    L1.x = __float2bfloat16(v.z - __bfloat162float(h2));
    L1.y = __float2bfloat16(v.w - __bfloat162float(h3));
    H[2*i] = H0; H[2*i+1] = H1; L[2*i] = L0; L[2*i+1] = L1;
}
__global__ void __launch_bounds__(256) k_split(const float* __restrict__ in2){
    int i = blockIdx.x*256 + threadIdx.x;
    split4(((const float4*)in2)[i], (__nv_bfloat162*)g_2h, (__nv_bfloat162*)g_2l, i);
}
__global__ void __launch_bounds__(256) k_splitw(const float* __restrict__ w){
    int i = blockIdx.x*256 + threadIdx.x;
    split4(((const float4*)w)[i], (__nv_bfloat162*)g_wh, (__nv_bfloat162*)g_wl, i);
}

// ---------------- K1: 2x2 max+mean pool of input1 -> (B,N,C) ----------------
__global__ void __launch_bounds__(256) k_pool1(const float* __restrict__ in1){
    __shared__ float tile[64][65];
    int ny = blockIdx.x, c0 = blockIdx.y * 64, b = blockIdx.z;
    int tid = threadIdx.x;
    #pragma unroll
    for (int p = 0; p < 16; p++){
        int l = p*256 + tid;
        int nx = l & 63, cc = l >> 6;
        const float* base = in1 + (((b*CC + c0+cc)*HW + 2*ny)*HW + 2*nx);
        float2 r0 = *(const float2*)base;
        float2 r1 = *(const float2*)(base + HW);
        float m = fmaxf(fmaxf(r0.x, r0.y), fmaxf(r1.x, r1.y));
        float s = (r0.x + r0.y + r1.x + r1.y) * 0.25f;
        tile[cc][nx] = m + s;
    }
    __syncthreads();
    #pragma unroll
    for (int p = 0; p < 16; p++){
        int l = p*256 + tid;
        int c = l & 63, nx = l >> 6;
        g_P1[(b*NN + ny*64 + nx)*CC + c0 + c] = tile[c][nx];
    }
}

// ---------------- K2: mma.sync bf16-split GEMM + bias + 2x2 pool -> g_P2 ----------------
// CTA: 128 o x 64 px (2 sy-rows x 32 x). K=256, k32 stages, 3-deep cp.async pipeline.
// 2 CTAs/SM. smem stage 24KB: A[split][o128][k32] (64B rows, chunk^((o>>1)&3)),
// B[split][k32][n64] (128B rows, chunk^(k&7)), n = sy*32 + x.
// 8 warps = 4(wm: 32 o) x 2(wn: 32 px). 3-term split: Ah*Bh + Al*Bh + Ah*Bl.
#define ASTG 16384
#define BSTG 8192
#define STAGE_SZ (ASTG + BSTG)          // 24576
#define GEMM_SMEM (3*STAGE_SZ)          // 73728

__global__ void __launch_bounds__(256, 2) k_gemm(const float* __restrict__ b_in){
    extern __shared__ char smem[];
    uint32_t sb = smem_u32(smem);
    float* Cs = (float*)smem;           // 128 x 68 f32 staging (reuses stage mem)

    int tid = threadIdx.x;
    int lane = tid & 31, wid = tid >> 5;
    int wm = wid >> 1, wn = wid & 1;    // 4 x 2 warps
    int bid = blockIdx.x;               // (((b*64+ny)*4+xq)*4 + ot): ot fastest for L2 B-reuse
    int ot = bid & 3;
    int xq = (bid >> 2) & 3;
    int ny = (bid >> 4) & 63;
    int b  = bid >> 10;
    int o0 = ot * 128;

    const __nv_bfloat16* Bsrc[2] = { g_2h, g_2l };
    const __nv_bfloat16* Asrc[2] = { g_wh, g_wl };

    float acc[2][4][4];
    #pragma unroll
    for (int i = 0; i < 2; i++)
        #pragma unroll
        for (int j = 0; j < 4; j++)
            #pragma unroll
            for (int q = 0; q < 4; q++) acc[i][j][q] = 0.f;

    auto load_stage = [&](int kc){
        uint32_t st = sb + (kc % 3)*STAGE_SZ;
        #pragma unroll
        for (int q = 0; q < 4; q++){            // A: 1024 x 16B
            int id = q*256 + tid;
            int sp = id >> 9, o = (id >> 2) & 127, c = id & 3;
            int cs = c ^ ((o >> 1) & 3);
            cp16(st + sp*8192 + o*64 + cs*16,
                 Asrc[sp] + (o0 + o)*CIN + kc*32 + c*8);
        }
        #pragma unroll
        for (int q = 0; q < 2; q++){            // B: 512 x 16B
            int id = q*256 + tid;
            int sp = id >> 8, k = (id >> 3) & 31, c = id & 7;
            int cs = c ^ (k & 7);
            int sy = c >> 2, x0 = (c & 3) << 3;
            cp16(st + ASTG + sp*4096 + k*128 + cs*16,
                 Bsrc[sp] + (size_t)(b*CIN + kc*32 + k)*(HW*HW)
                          + (2*ny + sy)*HW + xq*32 + x0);
        }
        CP_COMMIT();
    };

    load_stage(0);
    load_stage(1);

    int l15 = lane & 15, lh = lane >> 4;
    int g2 = lane >> 3;
    int bk_off = (g2 & 1)*8 + (lane & 7);
    int bn_off = (g2 >> 1)*8;

    for (int kc = 0; kc < 8; kc++){
        if (kc < 7) { CP_WAIT(1); } else { CP_WAIT(0); }
        __syncthreads();
        if (kc < 6) load_stage(kc + 2);
        uint32_t st = sb + (kc % 3)*STAGE_SZ;

        #pragma unroll
        for (int ks = 0; ks < 2; ks++){
            uint32_t Ah[2][4], Al[2][4];
            #pragma unroll
            for (int mf = 0; mf < 2; mf++){
                int r = wm*32 + mf*16 + l15;
                int c = ks*2 + lh;
                int cs = c ^ ((r >> 1) & 3);
                uint32_t base = st + r*64 + cs*16;
                ldsm4(Ah[mf], base);
                ldsm4(Al[mf], base + 8192);
            }
            uint32_t Bh[2][4], Bl[2][4];
            #pragma unroll
            for (int nf2 = 0; nf2 < 2; nf2++){
                int k = ks*16 + bk_off;
                int n = wn*32 + nf2*16 + bn_off;
                int c = n >> 3;
                int cs = c ^ (k & 7);
                uint32_t base = st + ASTG + k*128 + cs*16;
                ldsm4t(Bh[nf2], base);
                ldsm4t(Bl[nf2], base + 4096);
            }
            #pragma unroll
            for (int mf = 0; mf < 2; mf++)
                #pragma unroll
                for (int nf = 0; nf < 4; nf++){
                    const uint32_t* bh = &Bh[nf >> 1][(nf & 1)*2];
                    const uint32_t* bl = &Bl[nf >> 1][(nf & 1)*2];
                    mma16816(acc[mf][nf], Ah[mf], bh);
                    mma16816(acc[mf][nf], Al[mf], bh);
                    mma16816(acc[mf][nf], Ah[mf], bl);
                }
        }
        __syncthreads();
    }

    // ---- epilogue: stage C, 2x2 pool (max + mean), +2*bias ----
    #pragma unroll
    for (int mf = 0; mf < 2; mf++)
        #pragma unroll
        for (int nf = 0; nf < 4; nf++){
            int row = wm*32 + mf*16 + (lane >> 2);
            int col = wn*32 + nf*8 + (lane & 3)*2;
            *(float2*)&Cs[row*68 + col]     = make_float2(acc[mf][nf][0], acc[mf][nf][1]);
            *(float2*)&Cs[(row+8)*68 + col] = make_float2(acc[mf][nf][2], acc[mf][nf][3]);
        }
    __syncthreads();

    int pn_base = b*NN + ny*64 + xq*16;
    #pragma unroll
    for (int j = 0; j < 8; j++){
        int idx = j*256 + tid;
        int o = idx & 127, i = idx >> 7;        // o 0..127, pooled px i 0..15
        float2 v0 = *(const float2*)&Cs[o*68 + 2*i];        // sy=0
        float2 v1 = *(const float2*)&Cs[o*68 + 32 + 2*i];   // sy=1
        float m = fmaxf(fmaxf(v0.x, v0.y), fmaxf(v1.x, v1.y));
        float s = (v0.x + v0.y + v1.x + v1.y) * 0.25f;
        g_P2[(pn_base + i)*CC + o0 + o] = m + s + 2.f*b_in[o0 + o];
    }
}

// ---------------- K3: q/k = focus(lrelu(p + pos) / scale) ----------------
__global__ void __launch_bounds__(256) k_focus(const float* __restrict__ pos1,
                                               const float* __restrict__ pos2){
    int warp = threadIdx.x >> 5, lane = threadIdx.x & 31;
    int r = blockIdx.x * 8 + warp;
    int b = r >> 12, n = r & (NN - 1);
    const float* p1 = &g_P1[(b*NN + n)*CC];
    const float* p2 = &g_P2[(b*NN + n)*CC];
    const float* q1 = &pos1[n*CC];
    const float* q2 = &pos2[n*CC];
    float tq3[16], tk3[16];
    float s2q = 0.f, s6q = 0.f, s2k = 0.f, s6k = 0.f;
    #pragma unroll
    for (int i = 0; i < 4; i++){
        int c = i*128 + lane*4;
        float4 a  = *(const float4*)(p1 + c);
        float4 pa = *(const float4*)(q1 + c);
        float4 kk = *(const float4*)(p2 + c);
        float4 pk = *(const float4*)(q2 + c);
        float4 is = *(const float4*)(g_isc + c);
        float ta[4] = { lrelu(a.x + pa.x)*is.x, lrelu(a.y + pa.y)*is.y,
                        lrelu(a.z + pa.z)*is.z, lrelu(a.w + pa.w)*is.w };
        float tb[4] = { lrelu(kk.x + pk.x)*is.x, lrelu(kk.y + pk.y)*is.y,
                        lrelu(kk.z + pk.z)*is.z, lrelu(kk.w + pk.w)*is.w };
        #pragma unroll
        for (int j = 0; j < 4; j++){
            float t2 = ta[j]*ta[j]; float t3 = t2*ta[j];
            s2q += t2; s6q += t3*t3; tq3[i*4+j] = t3;
            float u2 = tb[j]*tb[j]; float u3 = u2*tb[j];
            s2k += u2; s6k += u3*u3; tk3[i*4+j] = u3;
        }
    }
    #pragma unroll
    for (int off = 16; off; off >>= 1){
        s2q += __shfl_xor_sync(0xffffffffu, s2q, off);
        s6q += __shfl_xor_sync(0xffffffffu, s6q, off);
        s2k += __shfl_xor_sync(0xffffffffu, s2k, off);
        s6k += __shfl_xor_sync(0xffffffffu, s6k, off);
    }
    float rq = sqrtf(s2q / s6q);
    float rk = sqrtf(s2k / s6k);
    #pragma unroll
    for (int i = 0; i < 4; i++){
        int c = i*128 + lane*4;
        *(float4*)&g_Q[(b*NN + n)*CC + c] =
            make_float4(rq*tq3[i*4], rq*tq3[i*4+1], rq*tq3[i*4+2], rq*tq3[i*4+3]);
        *(float4*)&g_K[(b*NN + n)*CC + c] =
            make_float4(rk*tk3[i*4], rk*tk3[i*4+1], rk*tk3[i*4+2], rk*tk3[i*4+3]);
    }
}

// ---------------- K4: kv ----------------
__global__ void __launch_bounds__(256) k_kv(){
    __shared__ float ks[64][HD];
    __shared__ float vs[64][HD];
    __shared__ float red[256*16];
    int bh = blockIdx.x;
    int b = bh >> 4, h = bh & 15;
    int tid = threadIdx.x;
    int g  = tid >> 6;
    int t6 = tid & 63;
    int ty = t6 >> 3, tx = t6 & 7;
    float acc[4][4] = {};
    const float* Kb = &g_K [(b*NN)*CC + h*HD];
    const float* Vb = &g_P2[(b*NN)*CC + h*HD];
    for (int ch = 0; ch < 64; ch++){
        #pragma unroll
        for (int p = 0; p < 8; p++){
            int l = p*256 + tid;
            int d = l & 31, nn = l >> 5;
            ks[nn][d] = Kb[(ch*64 + nn)*CC + d];
            vs[nn][d] = Vb[(ch*64 + nn)*CC + d];
        }
        __syncthreads();
        #pragma unroll
        for (int q = 0; q < 16; q++){
            int n = g*16 + q;
            float4 kk = *(const float4*)&ks[n][ty*4];
            float4 vv = *(const float4*)&vs[n][tx*4];
            float ka[4] = {kk.x, kk.y, kk.z, kk.w};
            float va[4] = {vv.x, vv.y, vv.z, vv.w};
            #pragma unroll
            for (int i = 0; i < 4; i++)
                #pragma unroll
                for (int j = 0; j < 4; j++) acc[i][j] += ka[i]*va[j];
        }
        __syncthreads();
    }
    #pragma unroll
    for (int i = 0; i < 4; i++)
        #pragma unroll
        for (int j = 0; j < 4; j++) red[tid*16 + i*4 + j] = acc[i][j];
    __syncthreads();
    if (tid < 64){
        #pragma unroll
        for (int idx = 0; idx < 16; idx++){
            float s = red[tid*16 + idx] + red[(tid+64)*16 + idx]
                    + red[(tid+128)*16 + idx] + red[(tid+192)*16 + idx];
            int i = idx >> 2, j = idx & 3;
            int d = (tid >> 3)*4 + i, e = (tid & 7)*4 + j;
            g_KV[(bh*HD + d)*HD + e] = s * (1.0f/NN);
        }
    }
}

// ---------------- K5: attn ----------------
__global__ void __launch_bounds__(256) k_attn(const float* __restrict__ w_v,
                                              const float* __restrict__ b_v){
    __shared__ float qs [128][HD];
    __shared__ float vsm[128][HD];
    __shared__ float osm[HD][128];
    int bh = blockIdx.x, seg = blockIdx.y;
    int b = bh >> 4, h = bh & 15;
    int tid = threadIdx.x;
    int e = tid & 31, grp = tid >> 5;
    float kvc[32], wv[32];
    #pragma unroll
    for (int d = 0; d < 32; d++){
        kvc[d] = g_KV[(bh*HD + d)*HD + e];
        wv[d]  = w_v[e*HD + d];
    }
    float bve = b_v[e];
    const float* Qb = &g_Q [(b*NN)*CC + h*HD];
    const float* Vb = &g_P2[(b*NN)*CC + h*HD];
    float* Ob = &g_ATT[(b*CC + h*HD)*NN];
    for (int cc = 0; cc < 8; cc++){
        int n0 = seg*1024 + cc*128;
        #pragma unroll
        for (int p = 0; p < 16; p++){
            int l = p*256 + tid;
            int d = l & 31, nn = l >> 5;
            qs [nn][d] = Qb[(n0 + nn)*CC + d];
            vsm[nn][d] = Vb[(n0 + nn)*CC + d];
        }
        __syncthreads();
        #pragma unroll
        for (int q = 0; q < 16; q++){
            int nn = grp*16 + q;
            float x = 0.f, vc = 0.f;
            #pragma unroll
            for (int d = 0; d < 32; d++){
                x  += qs [nn][d] * kvc[d];
                vc += vsm[nn][d] * wv[d];
            }
            osm[e][nn] = x + lrelu(vc + bve);
        }
        __syncthreads();
        #pragma unroll
        for (int p = 0; p < 16; p++){
            int l = p*256 + tid;
            int nn = l & 127, ee = l >> 7;
            Ob[ee*NN + n0 + nn] = osm[ee][nn];
        }
        __syncthreads();
    }
}

// ---------------- K6: bilinear upsample + sigmoid ----------------
__global__ void __launch_bounds__(256) k_upsample(float* __restrict__ out){
    int x  = threadIdx.x & 127, ys = threadIdx.x >> 7;
    int y  = blockIdx.x*2 + ys;
    int c  = blockIdx.y, b = blockIdx.z;
    const float S = 63.f / 127.f;
    float tyf = (float)y * S; int y0 = (int)tyf; if (y0 > 62) y0 = 62; float wy = tyf - (float)y0;
    float txf = (float)x * S; int x0 = (int)txf; if (x0 > 62) x0 = 62; float wx = txf - (float)x0;
    const float* att = &g_ATT[(b*CC + c)*NN];
    float a00 = att[y0*64 + x0    ], a01 = att[y0*64 + x0 + 1];
    float a10 = att[(y0+1)*64 + x0], a11 = att[(y0+1)*64 + x0 + 1];
    float r0 = a00*(1.f - wx) + a01*wx;
    float r1 = a10*(1.f - wx) + a11*wx;
    float v  = r0*(1.f - wy) + r1*wy;
    out[((b*CC + c)*HW + y)*HW + x] = 1.f / (1.f + expf(-v));
}

// ---------------- launch ----------------
extern "C" void kernel_launch(void* const* d_in, const int* in_sizes, int n_in,
                              void* d_out, int out_size){
    const float* input1 = (const float*)d_in[0];
    const float* input2 = (const float*)d_in[1];
    const float* w_in   = (const float*)d_in[2];
    const float* b_in   = (const float*)d_in[3];
    const float* w_v    = (const float*)d_in[4];
    const float* b_v    = (const float*)d_in[5];
    const float* sparam = (const float*)d_in[6];
    const float* pos1   = (const float*)d_in[7];
    const float* pos2   = (const float*)d_in[8];
    float* out = (float*)d_out;

    cudaFuncSetAttribute(k_gemm, cudaFuncAttributeMaxDynamicSharedMemorySize, GEMM_SMEM);

    k_scale    <<<1, CC>>>(sparam);
    k_splitw   <<<128, 256>>>(w_in);
    k_split    <<<32768, 256>>>(input2);
    k_pool1    <<<dim3(64, 8, 8), 256>>>(input1);
    k_gemm     <<<8192, 256, GEMM_SMEM>>>(b_in);
    k_focus    <<<4096, 256>>>(pos1, pos2);
    k_kv       <<<128, 256>>>();
    k_attn     <<<dim3(128, 4), 256>>>(w_v, b_v);
    k_upsample <<<dim3(64, 512, 8), 256>>>(out);
}